// round 10
// baseline (speedup 1.0000x reference)
#include <cuda_runtime.h>
#include <math.h>

#define BB   2
#define HH   16
#define TT   2048
#define DH   64
#define DD   1024
#define NC   10      // top-k candidates carried into fp64 re-rank (k=8 + 2 margin)

// -------- scratch (device globals; no allocation allowed) --------
__device__ float g_q[BB*HH*TT*DH];
__device__ float g_k[BB*HH*TT*DH];
__device__ float g_v[BB*HH*TT*DH];
__device__ float g_att[BB*TT*DD];

// ============================================================================
// SGEMM (NT): C[m][n] = sum_k A[m][k] * B[n][k]
// BM=BN=128, BK=16, 256 threads, 8x8 per thread.
// Two-level accumulation (flush every 32 k-steps) to shorten the fp32 rounding
// chain (~4x lower accumulation error), register prefetch of the next k-tile.
// A == nullptr  -> read A from the device-global g_att (out-proj input).
// scatter == 1  -> QKV projection: scatter into g_q/g_k/g_v, head-split layout.
// Requires K % 32 == 0 (K = 1024 for both uses).
// ============================================================================
__global__ __launch_bounds__(256)
void sgemm_nt(const float* __restrict__ A, const float* __restrict__ B,
              float* __restrict__ C, int M, int N, int K, int scatter)
{
    __shared__ float As[16][132];
    __shared__ float Bs[16][132];

    const float* Abase = A ? A : (const float*)g_att;

    const int tid = threadIdx.x;
    const int m0  = blockIdx.y * 128;
    const int n0  = blockIdx.x * 128;
    const int tx  = tid & 15;
    const int ty  = tid >> 4;
    const int lr  = tid >> 2;          // 0..63
    const int lc  = (tid & 3) << 2;    // 0,4,8,12

    float acc[8][8];
    float cacc[8][8];
    #pragma unroll
    for (int i = 0; i < 8; i++)
        #pragma unroll
        for (int j = 0; j < 8; j++) { acc[i][j] = 0.f; cacc[i][j] = 0.f; }

    const float* Ap = Abase + (size_t)(m0 + lr) * K + lc;
    const float* Bp = B     + (size_t)(n0 + lr) * K + lc;

    // prologue: load first k-tile into registers
    float4 a0 = *(const float4*)(Ap);
    float4 a1 = *(const float4*)(Ap + (size_t)64 * K);
    float4 b0 = *(const float4*)(Bp);
    float4 b1 = *(const float4*)(Bp + (size_t)64 * K);

    for (int k0 = 0; k0 < K; k0 += 16) {
        __syncthreads();   // previous tile's compute done
        As[lc+0][lr]    = a0.x; As[lc+1][lr]    = a0.y; As[lc+2][lr]    = a0.z; As[lc+3][lr]    = a0.w;
        As[lc+0][lr+64] = a1.x; As[lc+1][lr+64] = a1.y; As[lc+2][lr+64] = a1.z; As[lc+3][lr+64] = a1.w;
        Bs[lc+0][lr]    = b0.x; Bs[lc+1][lr]    = b0.y; Bs[lc+2][lr]    = b0.z; Bs[lc+3][lr]    = b0.w;
        Bs[lc+0][lr+64] = b1.x; Bs[lc+1][lr+64] = b1.y; Bs[lc+2][lr+64] = b1.z; Bs[lc+3][lr+64] = b1.w;
        __syncthreads();

        // prefetch next tile (hidden under compute)
        int kn = k0 + 16;
        if (kn < K) {
            a0 = *(const float4*)(Ap + kn);
            a1 = *(const float4*)(Ap + (size_t)64 * K + kn);
            b0 = *(const float4*)(Bp + kn);
            b1 = *(const float4*)(Bp + (size_t)64 * K + kn);
        }

        #pragma unroll
        for (int kk = 0; kk < 16; kk++) {
            float a[8], b[8];
            *(float4*)&a[0] = *(const float4*)&As[kk][ty*8];
            *(float4*)&a[4] = *(const float4*)&As[kk][ty*8 + 4];
            *(float4*)&b[0] = *(const float4*)&Bs[kk][tx*8];
            *(float4*)&b[4] = *(const float4*)&Bs[kk][tx*8 + 4];
            #pragma unroll
            for (int i = 0; i < 8; i++)
                #pragma unroll
                for (int j = 0; j < 8; j++)
                    cacc[i][j] = fmaf(a[i], b[j], cacc[i][j]);
        }

        if (k0 & 16) {   // flush every 32 k-steps (K % 32 == 0)
            #pragma unroll
            for (int i = 0; i < 8; i++)
                #pragma unroll
                for (int j = 0; j < 8; j++) { acc[i][j] += cacc[i][j]; cacc[i][j] = 0.f; }
        }
    }

    if (!scatter) {
        #pragma unroll
        for (int i = 0; i < 8; i++) {
            float* cp = C + (size_t)(m0 + ty*8 + i) * N + n0 + tx*8;
            *(float4*)cp       = make_float4(acc[i][0], acc[i][1], acc[i][2], acc[i][3]);
            *(float4*)(cp + 4) = make_float4(acc[i][4], acc[i][5], acc[i][6], acc[i][7]);
        }
    } else {
        #pragma unroll
        for (int i = 0; i < 8; i++) {
            int t  = m0 + ty*8 + i;
            int b_ = t >> 11;          // /2048
            int tl = t & 2047;
            #pragma unroll
            for (int j = 0; j < 8; j++) {
                int o    = n0 + tx*8 + j;
                int part = o >> 10;        // 0=q 1=k 2=v
                int rem  = o & 1023;
                int h    = rem >> 6;
                int dhi  = rem & 63;
                float* dst = (part == 0) ? g_q : (part == 1) ? g_k : g_v;
                dst[(((size_t)(b_*HH + h)) * TT + tl) * DH + dhi] = acc[i][j];
            }
        }
    }
}

// ============================================================================
// Fused causal scores + streaming top-10 + fp64 re-rank + softmax + sparse AV.
// Grid: (32 = B*H, 64 = T/32). CTA: 256 threads = 8 warps x 4 rows = 32 rows.
// Pass 1 (fp32): lane-local top-8 in registers; warp merge to top-10 candidates.
// Pass 2 (fp64): recompute candidate scores exactly (warp-cooperative dot) so
// the final top-8 selection matches the true ordering; softmax over kept
// (rank < keff, matching the reference's >= thresh rule) and gather <=8 V rows.
// ============================================================================
__device__ __forceinline__ void topk_insert(float v[8], int ix[8], float s, int j)
{
    float cv = s; int ci = j;
    #pragma unroll
    for (int p = 0; p < 8; p++) {
        if (cv > v[p]) {
            float tvv = v[p]; int tii = ix[p];
            v[p] = cv; ix[p] = ci;
            cv = tvv; ci = tii;
        }
    }
}

__global__ __launch_bounds__(256)
void attn_topk_kernel()
{
    __shared__ float ks[32 * 68];
    __shared__ float qs[32 * 68];

    const int bh   = blockIdx.x;
    const int qt   = (int)gridDim.y - 1 - (int)blockIdx.y;  // heavy tiles first
    const int row0 = qt * 32;
    const int tid  = threadIdx.x;
    const int wid  = tid >> 5;
    const int lane = tid & 31;

    const float* Qb = g_q + (size_t)bh * TT * DH;
    const float* Kb = g_k + (size_t)bh * TT * DH;
    const float* Vb = g_v + (size_t)bh * TT * DH;

    // load Q tile (32 rows x 64) into padded smem
    for (int idx = tid; idx < 32 * 16; idx += 256) {
        int r = idx >> 4, c = (idx & 15) << 2;
        *(float4*)&qs[r * 68 + c] = *(const float4*)(Qb + (size_t)(row0 + r) * DH + c);
    }

    const int rbase = wid * 4;
    const int g0    = row0 + rbase;

    float tv[4][8];
    int   ti[4][8];
    #pragma unroll
    for (int r = 0; r < 4; r++)
        #pragma unroll
        for (int p = 0; p < 8; p++) { tv[r][p] = -INFINITY; ti[r][p] = 0; }

    const float4* qp0 = (const float4*)(qs + (rbase + 0) * 68);
    const float4* qp1 = (const float4*)(qs + (rbase + 1) * 68);
    const float4* qp2 = (const float4*)(qs + (rbase + 2) * 68);
    const float4* qp3 = (const float4*)(qs + (rbase + 3) * 68);
    const float4* kp  = (const float4*)(ks + lane * 68);

    const int ntiles = qt + 1;

    // prologue: prefetch K tile 0 into registers (2 float4 per thread)
    int pr0 = tid >> 4,          pc0 = (tid & 15) << 2;
    int pr1 = (tid + 256) >> 4,  pc1 = ((tid + 256) & 15) << 2;
    float4 rk0 = *(const float4*)(Kb + (size_t)pr0 * DH + pc0);
    float4 rk1 = *(const float4*)(Kb + (size_t)pr1 * DH + pc1);

    for (int tj = 0; tj < ntiles; tj++) {
        int j0 = tj << 5;
        __syncthreads();
        *(float4*)&ks[pr0 * 68 + pc0] = rk0;
        *(float4*)&ks[pr1 * 68 + pc1] = rk1;
        __syncthreads();
        if (tj + 1 < ntiles) {
            int jn = (tj + 1) << 5;
            rk0 = *(const float4*)(Kb + (size_t)(jn + pr0) * DH + pc0);
            rk1 = *(const float4*)(Kb + (size_t)(jn + pr1) * DH + pc1);
        }

        float s0 = 0.f, s1 = 0.f, s2 = 0.f, s3 = 0.f;
        #pragma unroll
        for (int d = 0; d < 16; d++) {
            float4 kv = kp[d];
            float4 q;
            q = qp0[d];
            s0 = fmaf(kv.x, q.x, s0); s0 = fmaf(kv.y, q.y, s0);
            s0 = fmaf(kv.z, q.z, s0); s0 = fmaf(kv.w, q.w, s0);
            q = qp1[d];
            s1 = fmaf(kv.x, q.x, s1); s1 = fmaf(kv.y, q.y, s1);
            s1 = fmaf(kv.z, q.z, s1); s1 = fmaf(kv.w, q.w, s1);
            q = qp2[d];
            s2 = fmaf(kv.x, q.x, s2); s2 = fmaf(kv.y, q.y, s2);
            s2 = fmaf(kv.z, q.z, s2); s2 = fmaf(kv.w, q.w, s2);
            q = qp3[d];
            s3 = fmaf(kv.x, q.x, s3); s3 = fmaf(kv.y, q.y, s3);
            s3 = fmaf(kv.z, q.z, s3); s3 = fmaf(kv.w, q.w, s3);
        }
        int j = j0 + lane;
        s0 *= 0.125f; s1 *= 0.125f; s2 *= 0.125f; s3 *= 0.125f;
        if (j <= g0 + 0 && s0 > tv[0][7]) topk_insert(tv[0], ti[0], s0, j);
        if (j <= g0 + 1 && s1 > tv[1][7]) topk_insert(tv[1], ti[1], s1, j);
        if (j <= g0 + 2 && s2 > tv[2][7]) topk_insert(tv[2], ti[2], s2, j);
        if (j <= g0 + 3 && s3 > tv[3][7]) topk_insert(tv[3], ti[3], s3, j);
    }

    const int b_ = bh >> 4;
    const int h  = bh & 15;

    #pragma unroll
    for (int r = 0; r < 4; r++) {
        int gi = g0 + r;

        // ---- merge lane-local top-8 -> global top-NC candidate indices ----
        int mi[NC];
        #pragma unroll
        for (int n = 0; n < NC; n++) {
            float head = tv[r][0];
            float best = head;
            #pragma unroll
            for (int off = 16; off > 0; off >>= 1)
                best = fmaxf(best, __shfl_xor_sync(0xffffffffu, best, off));
            unsigned bal = __ballot_sync(0xffffffffu, head == best);
            int owner = __ffs((int)bal) - 1;
            int idx = __shfl_sync(0xffffffffu, ti[r][0], owner);
            mi[n] = (best == -INFINITY) ? -1 : idx;
            if (lane == owner) {
                #pragma unroll
                for (int p = 0; p < 7; p++) { tv[r][p] = tv[r][p + 1]; ti[r][p] = ti[r][p + 1]; }
                tv[r][7] = -INFINITY;
            }
        }

        // ---- fp64 exact recompute of candidate scores (warp-cooperative) ----
        const float* qrow = qs + (rbase + r) * 68;
        float q1 = qrow[lane];
        float q2 = qrow[lane + 32];
        double dv[NC];
        #pragma unroll
        for (int n = 0; n < NC; n++) {
            int j = mi[n];
            double p = 0.0;
            if (j >= 0) {
                const float* kr = Kb + (size_t)j * DH;
                p = (double)q1 * (double)kr[lane] + (double)q2 * (double)kr[lane + 32];
            }
            #pragma unroll
            for (int off = 16; off > 0; off >>= 1)
                p += __shfl_xor_sync(0xffffffffu, p, off);
            dv[n] = (j >= 0) ? p * 0.125 : -1.0e300;
        }

        // ---- select top keff by fp64 rank; softmax; sparse AV ----
        int keff = min(gi + 1, 8);
        double mx = dv[0];
        #pragma unroll
        for (int n = 1; n < NC; n++) if (dv[n] > mx) mx = dv[n];

        float w[NC];
        float den = 0.f;
        #pragma unroll
        for (int n = 0; n < NC; n++) {
            int rank = 0;
            #pragma unroll
            for (int m = 0; m < NC; m++) rank += (dv[m] > dv[n]) ? 1 : 0;
            bool keep = (mi[n] >= 0) && (rank < keff);
            float wn = keep ? __expf((float)(dv[n] - mx)) : 0.f;
            w[n] = wn;
            den += wn;
        }

        float o0 = 0.f, o1 = 0.f;
        #pragma unroll
        for (int n = 0; n < NC; n++) {
            if (w[n] > 0.f) {   // uniform across warp (mi, dv identical on all lanes)
                const float* vr = Vb + (size_t)mi[n] * DH;
                o0 = fmaf(w[n], vr[lane],      o0);
                o1 = fmaf(w[n], vr[lane + 32], o1);
            }
        }
        float inv = 1.f / den;
        float* op = g_att + ((size_t)b_ * TT + gi) * DD + h * DH;
        op[lane]      = o0 * inv;
        op[lane + 32] = o1 * inv;
    }
}

// ============================================================================
// launch — three kernel launches only; no CUDA API calls in the capture path.
// ============================================================================
extern "C" void kernel_launch(void* const* d_in, const int* in_sizes, int n_in,
                              void* d_out, int out_size)
{
    const float* x     = (const float*)d_in[0];   // (2,2048,1024)
    const float* w_qkv = (const float*)d_in[1];   // (3072,1024)
    const float* w_out = (const float*)d_in[2];   // (1024,1024)
    float* out = (float*)d_out;                   // (2,2048,1024)

    dim3 blk(256);
    // QKV projection + head-split scatter: M=4096, N=3072, K=1024
    sgemm_nt<<<dim3(3072 / 128, 4096 / 128), blk>>>(x, w_qkv, nullptr, 4096, 3072, 1024, 1);
    // fused causal scores + top-10 + fp64 re-rank + softmax + sparse AV
    attn_topk_kernel<<<dim3(BB * HH, TT / 32), blk>>>();
    // output projection: M=4096, N=1024, K=1024  (A = g_att via nullptr)
    sgemm_nt<<<dim3(1024 / 128, 4096 / 128), blk>>>(nullptr, w_out, out, 4096, 1024, 1024, 0);
}